// round 1
// baseline (speedup 1.0000x reference)
#include <cuda_runtime.h>
#include <cstdint>

// ---------------------------------------------------------------------------
// Problem constants (fixed shapes for this problem)
// ---------------------------------------------------------------------------
#define D_IN 992
#define HID  32
#define KC   32            // k-chunk per smem stage
#define TM   256           // rows per block (GEMM)
#define NCH  (D_IN / KC)   // 31 chunks
#define MAXN 300000

// Scratch: hidden activations stored TRANSPOSED [HID][N] for coalesced KAN loads
__device__ float g_hT[(size_t)HID * MAXN];

// ---------------------------------------------------------------------------
// f32x2 packed-math helpers (Blackwell FFMA2 path — only reachable via PTX)
// ---------------------------------------------------------------------------
__device__ __forceinline__ uint64_t f2dup(float x) {
    uint64_t r; asm("mov.b64 %0, {%1, %1};" : "=l"(r) : "f"(x)); return r;
}
__device__ __forceinline__ void f2unpack(uint64_t v, float& x, float& y) {
    asm("mov.b64 {%0, %1}, %2;" : "=f"(x), "=f"(y) : "l"(v));
}
__device__ __forceinline__ void ffma2(uint64_t& d, uint64_t a, uint64_t b) {
    asm("fma.rn.f32x2 %0, %1, %2, %0;" : "+l"(d) : "l"(a), "l"(b));
}

// ---------------------------------------------------------------------------
// GEMM: hidden^T[c][row] = sum_k A[row][k] * W[k][c] + bias[c]
// 256 threads; each thread: 4 rows x 8 cols in f32x2 accumulators.
// W (992x32 fp32, 124KB) fully staged in smem; A double-buffered in a
// XOR-swizzled [k][row] layout (conflict-free transpose STS + LDS.128).
// ---------------------------------------------------------------------------
__global__ void __launch_bounds__(256, 1)
gemm_kernel(const float* __restrict__ A, const float* __restrict__ W,
            const float* __restrict__ bias, int N)
{
    extern __shared__ float sm[];
    float* Ws = sm;                         // [992][32]
    float* As = sm + D_IN * HID;            // [2][KC][TM] (swizzled)

    const int tid  = threadIdx.x;
    const int row0 = blockIdx.x * TM;

    // Stage W (coalesced float4 copy)
    for (int idx = tid * 4; idx < D_IN * HID; idx += 256 * 4)
        *(float4*)&Ws[idx] = *(const float4*)&W[idx];

    // A-loader mapping: each thread owns k-quad kq (16B of a row), 8 rows
    const int kq    = tid & 7;      // 0..7  -> k = kq*4 + j within chunk
    const int rbase = tid >> 3;     // 0..31 -> rows rbase + 32*it
    float4 pf[8];

    // prefetch chunk 0
    #pragma unroll
    for (int it = 0; it < 8; it++) {
        int r   = rbase + it * 32;
        int row = min(row0 + r, N - 1);
        pf[it] = *(const float4*)&A[(size_t)row * D_IN + kq * 4];
    }
    // store chunk 0 into buffer 0
    #pragma unroll
    for (int it = 0; it < 8; it++) {
        int r = rbase + it * 32;
        // phys word = (kq*4+j)*TM + ((r>>2)^kq)*4 + (r&3)   (swizzle s(k)=kq)
        float* dst = &As[(kq * 4) * TM + (((r >> 2) ^ kq) << 2) + (r & 3)];
        dst[0 * TM] = pf[it].x; dst[1 * TM] = pf[it].y;
        dst[2 * TM] = pf[it].z; dst[3 * TM] = pf[it].w;
    }
    __syncthreads();

    const int mgrp = tid & 63;   // row quad (4 rows)
    const int ngrp = tid >> 6;   // col group (8 cols); uniform per warp -> W broadcast

    uint64_t acc[4][4];
    #pragma unroll
    for (int m = 0; m < 4; m++)
        #pragma unroll
        for (int j = 0; j < 4; j++) acc[m][j] = 0ull;

    int buf = 0;
    for (int c = 0; c < NCH; c++) {
        // prefetch next chunk (global -> regs)
        if (c + 1 < NCH) {
            int k0n = (c + 1) * KC;
            #pragma unroll
            for (int it = 0; it < 8; it++) {
                int r   = rbase + it * 32;
                int row = min(row0 + r, N - 1);
                pf[it] = *(const float4*)&A[(size_t)row * D_IN + k0n + kq * 4];
            }
        }
        // compute current chunk
        const float* Ab = &As[buf * (KC * TM)];
        const float* Wb = &Ws[(c * KC) * HID + ngrp * 8];
        #pragma unroll
        for (int kk = 0; kk < KC; kk++) {
            const int s = (kk >> 2) & 7;
            float4 av = *(const float4*)&Ab[kk * TM + (((mgrp ^ s)) << 2)];
            const uint64_t* wp = (const uint64_t*)(Wb + kk * HID);
            uint64_t w01 = wp[0], w23 = wp[1], w45 = wp[2], w67 = wp[3];
            uint64_t a;
            a = f2dup(av.x);
            ffma2(acc[0][0], a, w01); ffma2(acc[0][1], a, w23);
            ffma2(acc[0][2], a, w45); ffma2(acc[0][3], a, w67);
            a = f2dup(av.y);
            ffma2(acc[1][0], a, w01); ffma2(acc[1][1], a, w23);
            ffma2(acc[1][2], a, w45); ffma2(acc[1][3], a, w67);
            a = f2dup(av.z);
            ffma2(acc[2][0], a, w01); ffma2(acc[2][1], a, w23);
            ffma2(acc[2][2], a, w45); ffma2(acc[2][3], a, w67);
            a = f2dup(av.w);
            ffma2(acc[3][0], a, w01); ffma2(acc[3][1], a, w23);
            ffma2(acc[3][2], a, w45); ffma2(acc[3][3], a, w67);
        }
        __syncthreads();   // everyone done reading before overwriting other buffer
        if (c + 1 < NCH) {
            float* dstb = &As[(buf ^ 1) * (KC * TM)];
            #pragma unroll
            for (int it = 0; it < 8; it++) {
                int r = rbase + it * 32;
                float* dst = &dstb[(kq * 4) * TM + (((r >> 2) ^ kq) << 2) + (r & 3)];
                dst[0 * TM] = pf[it].x; dst[1 * TM] = pf[it].y;
                dst[2 * TM] = pf[it].z; dst[3 * TM] = pf[it].w;
            }
        }
        __syncthreads();
        buf ^= 1;
    }

    // Epilogue: bias + store transposed (columns of hT get contiguous rows)
    float bb[8];
    #pragma unroll
    for (int j = 0; j < 8; j++) bb[j] = __ldg(&bias[ngrp * 8 + j]);

    float v[4][8];
    #pragma unroll
    for (int m = 0; m < 4; m++) {
        f2unpack(acc[m][0], v[m][0], v[m][1]);
        f2unpack(acc[m][1], v[m][2], v[m][3]);
        f2unpack(acc[m][2], v[m][4], v[m][5]);
        f2unpack(acc[m][3], v[m][6], v[m][7]);
    }
    const int rb = row0 + 4 * mgrp;
    const bool fast = (rb + 3 < N) && ((N & 3) == 0);
    #pragma unroll
    for (int cc = 0; cc < 8; cc++) {
        int c4 = ngrp * 8 + cc;
        float4 o = make_float4(v[0][cc] + bb[cc], v[1][cc] + bb[cc],
                               v[2][cc] + bb[cc], v[3][cc] + bb[cc]);
        if (fast) {
            *(float4*)&g_hT[(size_t)c4 * N + rb] = o;
        } else {
            if (rb + 0 < N) g_hT[(size_t)c4 * N + rb + 0] = o.x;
            if (rb + 1 < N) g_hT[(size_t)c4 * N + rb + 1] = o.y;
            if (rb + 2 < N) g_hT[(size_t)c4 * N + rb + 2] = o.z;
            if (rb + 3 < N) g_hT[(size_t)c4 * N + rb + 3] = o.w;
        }
    }
}

// ---------------------------------------------------------------------------
// Degree-4 uniform B-spline basis via de Boor: t = (x+2)*4, u = t - floor(t).
// Returns the 5 nonzero basis values B4[c-4..c]. Matches reference recursion
// exactly (knot differences are p*h; normalized to integer knots).
// ---------------------------------------------------------------------------
__device__ __forceinline__ void bspline4(float u, float bw[5]) {
    const float um = 1.f - u;
    float c0 = um, c1 = u;
    float d0 = 0.5f * (um * c0);
    float d1 = 0.5f * ((u + 1.f) * c0 + (2.f - u) * c1);
    float d2 = 0.5f * (u * c1);
    const float i3 = 1.f / 3.f;
    float e0 = i3 * (um * d0);
    float e1 = i3 * ((u + 2.f) * d0 + (2.f - u) * d1);
    float e2 = i3 * ((u + 1.f) * d1 + (3.f - u) * d2);
    float e3 = i3 * (u * d2);
    bw[0] = 0.25f * (um * e0);
    bw[1] = 0.25f * ((u + 3.f) * e0 + (2.f - u) * e1);
    bw[2] = 0.25f * ((u + 2.f) * e1 + (3.f - u) * e2);
    bw[3] = 0.25f * ((u + 1.f) * e2 + (4.f - u) * e3);
    bw[4] = 0.25f * (u * e3);
}

__device__ __forceinline__ float silu_f(float x) {
    return x / (1.f + __expf(-x));
}

// ---------------------------------------------------------------------------
// KAN evaluation: one thread per row. Params pre-multiplied (coef*ws) and
// staged in smem with output-dim padded to 8 for f32x2 accumulation and
// aligned vector LDS (all broadcast reads).
// ---------------------------------------------------------------------------
__global__ void __launch_bounds__(256)
kan_kernel(const float* __restrict__ coef0, const float* __restrict__ wb0,
           const float* __restrict__ ws0,   const float* __restrict__ b0,
           const float* __restrict__ coef1, const float* __restrict__ wb1,
           const float* __restrict__ ws1,   const float* __restrict__ b1,
           float* __restrict__ out, int N)
{
    __shared__ __align__(16) float cw0s[32 * 12 * 8]; // [i][j][o pad 8] = coef0*ws0
    __shared__ __align__(16) float wb0s[32 * 8];      // [i][o pad 8]
    __shared__ __align__(16) float cw1s[6 * 12];      // [i][j] = coef1*ws1
    __shared__ float wb1s[6], b0s[6], b1s[1];

    const int tid = threadIdx.x;
    for (int idx = tid; idx < 32 * 12 * 8; idx += 256) {
        int i = idx / 96, rem = idx % 96, j = rem >> 3, o = rem & 7;
        cw0s[idx] = (o < 6) ? coef0[(i * 6 + o) * 12 + j] * ws0[i * 6 + o] : 0.f;
    }
    if (tid < 32 * 8) {
        int i = tid >> 3, o = tid & 7;
        wb0s[tid] = (o < 6) ? wb0[i * 6 + o] : 0.f;
    }
    if (tid < 72) cw1s[tid] = coef1[tid] * ws1[tid / 12];
    if (tid < 6)  { wb1s[tid] = wb1[tid]; b0s[tid] = b0[tid]; }
    if (tid == 0) b1s[0] = b1[0];
    __syncthreads();

    const int row = blockIdx.x * 256 + tid;
    if (row >= N) return;

    // coalesced loads from transposed hidden
    float xs[32];
    #pragma unroll
    for (int i = 0; i < 32; i++) xs[i] = __ldg(&g_hT[(size_t)i * N + row]);

    // ---- layer 0: 32 -> 6 ----
    uint64_t acc[4];
    acc[0] = acc[1] = acc[2] = acc[3] = 0ull;

    #pragma unroll
    for (int i = 0; i < 32; i++) {
        float x  = xs[i];
        float sg = silu_f(x);
        uint64_t sgd = f2dup(sg);
        const uint64_t* wbp = (const uint64_t*)&wb0s[i * 8];
        ffma2(acc[0], sgd, wbp[0]); ffma2(acc[1], sgd, wbp[1]);
        ffma2(acc[2], sgd, wbp[2]); ffma2(acc[3], sgd, wbp[3]);

        float t = (x + 2.f) * 4.f;
        if (t >= 0.f && t < 16.f) {
            float cf = floorf(t);
            int   c  = (int)cf;
            float u  = t - cf;
            float bw[5];
            bspline4(u, bw);
            #pragma unroll
            for (int k = 0; k < 5; k++) {
                int j = c - 4 + k;
                if (j >= 0 && j < 12) {
                    uint64_t bd = f2dup(bw[k]);
                    const uint64_t* cp = (const uint64_t*)&cw0s[i * 96 + j * 8];
                    ffma2(acc[0], bd, cp[0]); ffma2(acc[1], bd, cp[1]);
                    ffma2(acc[2], bd, cp[2]); ffma2(acc[3], bd, cp[3]);
                }
            }
        }
    }
    float hh[6], t0, t1;
    f2unpack(acc[0], hh[0], hh[1]);
    f2unpack(acc[1], hh[2], hh[3]);
    f2unpack(acc[2], t0, t1); hh[4] = t0; hh[5] = t1;

    // ---- layer 1: 6 -> 1 ----
    float res = b1s[0];
    #pragma unroll
    for (int i = 0; i < 6; i++) {
        float x  = hh[i] + b0s[i];
        res += silu_f(x) * wb1s[i];
        float t = (x + 2.f) * 4.f;
        if (t >= 0.f && t < 16.f) {
            float cf = floorf(t);
            int   c  = (int)cf;
            float u  = t - cf;
            float bw[5];
            bspline4(u, bw);
            #pragma unroll
            for (int k = 0; k < 5; k++) {
                int j = c - 4 + k;
                if (j >= 0 && j < 12) res += bw[k] * cw1s[i * 12 + j];
            }
        }
    }
    out[row] = res;
}

// ---------------------------------------------------------------------------
// Launch
// ---------------------------------------------------------------------------
extern "C" void kernel_launch(void* const* d_in, const int* in_sizes, int n_in,
                              void* d_out, int out_size)
{
    const float* node_rep = (const float*)d_in[0];
    const float* mlp_w    = (const float*)d_in[1];
    const float* mlp_b    = (const float*)d_in[2];
    const float* coef0    = (const float*)d_in[3];
    const float* wb0      = (const float*)d_in[4];
    const float* ws0      = (const float*)d_in[5];
    const float* b0       = (const float*)d_in[6];
    const float* coef1    = (const float*)d_in[7];
    const float* wb1      = (const float*)d_in[8];
    const float* ws1      = (const float*)d_in[9];
    const float* b1       = (const float*)d_in[10];

    int N = in_sizes[0] / D_IN;
    if (N > MAXN) N = MAXN;

    const size_t smem = (size_t)(D_IN * HID + 2 * KC * TM) * sizeof(float); // 192,512 B
    cudaFuncSetAttribute(gemm_kernel, cudaFuncAttributeMaxDynamicSharedMemorySize,
                         (int)smem);

    gemm_kernel<<<(N + TM - 1) / TM, 256, smem>>>(node_rep, mlp_w, mlp_b, N);
    kan_kernel<<<(N + 255) / 256, 256>>>(coef0, wb0, ws0, b0,
                                         coef1, wb1, ws1, b1,
                                         (float*)d_out, N);
}

// round 3
// speedup vs baseline: 1.7983x; 1.7983x over previous
#include <cuda_runtime.h>
#include <cuda_bf16.h>
#include <cstdint>

// ---------------------------------------------------------------------------
// Problem constants
// ---------------------------------------------------------------------------
#define D_IN   992
#define HID    32
#define NKS    62            // 992 / 16 k-steps
#define TMROWS 256           // rows per CTA (8 warps x 32 rows)

// W pre-converted to mma fragment layout, bf16 hi/lo split.
// layout: [ks 62][nt 4][lane 32][reg 2] uint32
__device__ uint32_t g_Wf_hi[NKS * 4 * 32 * 2];
__device__ uint32_t g_Wf_lo[NKS * 4 * 32 * 2];

// ---------------------------------------------------------------------------
// helpers
// ---------------------------------------------------------------------------
// pack two fp32 -> bf16x2, e0 in low half, e1 in high half
__device__ __forceinline__ uint32_t packbf(float e0, float e1) {
    uint32_t r;
    asm("cvt.rn.bf16x2.f32 %0, %1, %2;" : "=r"(r) : "f"(e1), "f"(e0));
    return r;
}
// bf16x2 -> the two fp32 values it represents
__device__ __forceinline__ void unpackbf(uint32_t p, float& e0, float& e1) {
    e0 = __uint_as_float(p << 16);
    e1 = __uint_as_float(p & 0xFFFF0000u);
}

__device__ __forceinline__ void mma_bf16(float d[4], uint32_t a0, uint32_t a1,
                                         uint32_t a2, uint32_t a3,
                                         uint32_t b0, uint32_t b1) {
    asm volatile(
        "mma.sync.aligned.m16n8k16.row.col.f32.bf16.bf16.f32 "
        "{%0,%1,%2,%3}, {%4,%5,%6,%7}, {%8,%9}, {%0,%1,%2,%3};"
        : "+f"(d[0]), "+f"(d[1]), "+f"(d[2]), "+f"(d[3])
        : "r"(a0), "r"(a1), "r"(a2), "r"(a3), "r"(b0), "r"(b1));
}

// f32x2 packed helpers for the KAN phase
__device__ __forceinline__ uint64_t f2dup(float x) {
    uint64_t r; asm("mov.b64 %0, {%1, %1};" : "=l"(r) : "f"(x)); return r;
}
__device__ __forceinline__ void f2unpack(uint64_t v, float& x, float& y) {
    asm("mov.b64 {%0, %1}, %2;" : "=f"(x), "=f"(y) : "l"(v));
}
__device__ __forceinline__ void ffma2(uint64_t& d, uint64_t a, uint64_t b) {
    asm("fma.rn.f32x2 %0, %1, %2, %0;" : "+l"(d) : "l"(a), "l"(b));
}

// degree-4 uniform B-spline basis (the 5 nonzero values), matches reference
__device__ __forceinline__ void bspline4(float u, float bw[5]) {
    const float um = 1.f - u;
    float c0 = um, c1 = u;
    float d0 = 0.5f * (um * c0);
    float d1 = 0.5f * ((u + 1.f) * c0 + (2.f - u) * c1);
    float d2 = 0.5f * (u * c1);
    const float i3 = 1.f / 3.f;
    float e0 = i3 * (um * d0);
    float e1 = i3 * ((u + 2.f) * d0 + (2.f - u) * d1);
    float e2 = i3 * ((u + 1.f) * d1 + (3.f - u) * d2);
    float e3 = i3 * (u * d2);
    bw[0] = 0.25f * (um * e0);
    bw[1] = 0.25f * ((u + 3.f) * e0 + (2.f - u) * e1);
    bw[2] = 0.25f * ((u + 2.f) * e1 + (3.f - u) * e2);
    bw[3] = 0.25f * ((u + 1.f) * e2 + (4.f - u) * e3);
    bw[4] = 0.25f * (u * e3);
}
__device__ __forceinline__ float silu_f(float x) { return x / (1.f + __expf(-x)); }

// ---------------------------------------------------------------------------
// W pre-conversion: fp32 [992][32] -> mma B-fragment bf16 hi/lo
// B frag (m16n8k16, col): lane (g = lane>>2, t4 = lane&3):
//   reg0 = { W[k0+2*t4][n], W[k0+2*t4+1][n] },  reg1 = rows +8,  n = nt*8+g
// ---------------------------------------------------------------------------
__global__ void wfrag_kernel(const float* __restrict__ W) {
    int idx = blockIdx.x * 256 + threadIdx.x;     // 62*4*32 = 7936
    if (idx >= NKS * 4 * 32) return;
    int lane = idx & 31;
    int nt   = (idx >> 5) & 3;
    int ks   = idx >> 7;
    int g = lane >> 2, t4 = lane & 3;
    int n  = nt * 8 + g;
    int k0 = ks * 16 + t4 * 2;

    float x0 = W[(k0    ) * HID + n];
    float x1 = W[(k0 + 1) * HID + n];
    float y0 = W[(k0 + 8) * HID + n];
    float y1 = W[(k0 + 9) * HID + n];

    uint32_t h0 = packbf(x0, x1), h1 = packbf(y0, y1);
    float hx0, hx1, hy0, hy1;
    unpackbf(h0, hx0, hx1);
    unpackbf(h1, hy0, hy1);
    uint32_t l0 = packbf(x0 - hx0, x1 - hx1);
    uint32_t l1 = packbf(y0 - hy0, y1 - hy1);

    g_Wf_hi[idx * 2 + 0] = h0;  g_Wf_hi[idx * 2 + 1] = h1;
    g_Wf_lo[idx * 2 + 0] = l0;  g_Wf_lo[idx * 2 + 1] = l1;
}

// ---------------------------------------------------------------------------
// Fused kernel: HMMA GEMM (hidden = A @ W + bias) -> smem transpose -> KAN
// CTA: 256 threads (8 warps), 256 rows. Warp w owns rows w*32 .. w*32+31
// (2 m16 tiles). N=32 = 4 n8 tiles. 3-pass bf16-split fp32 accumulation.
// ---------------------------------------------------------------------------
__global__ void __launch_bounds__(256)
fused_kernel(const float* __restrict__ A, const float* __restrict__ bias,
             const float* __restrict__ coef0, const float* __restrict__ wb0,
             const float* __restrict__ ws0,   const float* __restrict__ b0,
             const float* __restrict__ coef1, const float* __restrict__ wb1,
             const float* __restrict__ ws1,   const float* __restrict__ b1,
             float* __restrict__ out, int N)
{
    __shared__ __align__(16) float hs[TMROWS * 33];      // hidden, stride 33
    __shared__ __align__(16) float cw0s[32 * 12 * 8];    // coef0*ws0, o padded 8
    __shared__ __align__(16) float wb0s[32 * 8];
    __shared__ __align__(16) float cw1s[6 * 12];
    __shared__ float wb1s[6], b0s[6], b1s[1];

    const int tid  = threadIdx.x;
    const int warp = tid >> 5;
    const int lane = tid & 31;
    const int g    = lane >> 2;
    const int t4   = lane & 3;
    const int rowbase = blockIdx.x * TMROWS + warp * 32;

    // ---- stage KAN tables (overlaps with GEMM loads) ----
    for (int idx = tid; idx < 32 * 12 * 8; idx += 256) {
        int i = idx / 96, rem = idx % 96, j = rem >> 3, o = rem & 7;
        cw0s[idx] = (o < 6) ? coef0[(i * 6 + o) * 12 + j] * ws0[i * 6 + o] : 0.f;
    }
    if (tid < 32 * 8) {
        int i = tid >> 3, o = tid & 7;
        wb0s[tid] = (o < 6) ? wb0[i * 6 + o] : 0.f;
    }
    if (tid < 72) cw1s[tid] = coef1[tid] * ws1[tid / 12];
    if (tid < 6)  { wb1s[tid] = wb1[tid]; b0s[tid] = b0[tid]; }
    if (tid == 0) b1s[0] = b1[0];

    // ---- GEMM mainloop ----
    // clamped row pointers for A fragments: [mt][half(0:+0, 1:+8)]
    const float* Ap[2][2];
    #pragma unroll
    for (int mt = 0; mt < 2; mt++) {
        int r0 = rowbase + mt * 16 + g;
        int r1 = r0 + 8;
        if (r0 > N - 1) r0 = N - 1;
        if (r1 > N - 1) r1 = N - 1;
        Ap[mt][0] = A + (size_t)r0 * D_IN;
        Ap[mt][1] = A + (size_t)r1 * D_IN;
    }
    const int kcol = t4 * 2;

    float acc[2][4][4];
    #pragma unroll
    for (int mt = 0; mt < 2; mt++)
        #pragma unroll
        for (int nt = 0; nt < 4; nt++)
            #pragma unroll
            for (int r = 0; r < 4; r++) acc[mt][nt][r] = 0.f;

    #pragma unroll 2
    for (int ks = 0; ks < NKS; ks++) {
        const int k0 = ks * 16;

        // W fragments (hi/lo), broadcast across warps/CTAs -> L1 hits
        uint2 wh[4], wl[4];
        #pragma unroll
        for (int nt = 0; nt < 4; nt++) {
            int fo = ((ks * 4 + nt) * 32 + lane) * 2;
            wh[nt] = *(const uint2*)&g_Wf_hi[fo];
            wl[nt] = *(const uint2*)&g_Wf_lo[fo];
        }

        #pragma unroll
        for (int mt = 0; mt < 2; mt++) {
            float2 a01 = *(const float2*)(Ap[mt][0] + k0 + kcol);
            float2 a23 = *(const float2*)(Ap[mt][1] + k0 + kcol);
            float2 a45 = *(const float2*)(Ap[mt][0] + k0 + kcol + 8);
            float2 a67 = *(const float2*)(Ap[mt][1] + k0 + kcol + 8);

            uint32_t ah0 = packbf(a01.x, a01.y);
            uint32_t ah1 = packbf(a23.x, a23.y);
            uint32_t ah2 = packbf(a45.x, a45.y);
            uint32_t ah3 = packbf(a67.x, a67.y);

            float h0, h1;
            uint32_t al0, al1, al2, al3;
            unpackbf(ah0, h0, h1); al0 = packbf(a01.x - h0, a01.y - h1);
            unpackbf(ah1, h0, h1); al1 = packbf(a23.x - h0, a23.y - h1);
            unpackbf(ah2, h0, h1); al2 = packbf(a45.x - h0, a45.y - h1);
            unpackbf(ah3, h0, h1); al3 = packbf(a67.x - h0, a67.y - h1);

            #pragma unroll
            for (int nt = 0; nt < 4; nt++) {
                mma_bf16(acc[mt][nt], ah0, ah1, ah2, ah3, wh[nt].x, wh[nt].y);
                mma_bf16(acc[mt][nt], ah0, ah1, ah2, ah3, wl[nt].x, wl[nt].y);
                mma_bf16(acc[mt][nt], al0, al1, al2, al3, wh[nt].x, wh[nt].y);
            }
        }
    }

    // ---- epilogue: bias add + smem transpose (stride 33, conflict-light) ----
    #pragma unroll
    for (int nt = 0; nt < 4; nt++) {
        float2 bv = *(const float2*)&bias[nt * 8 + t4 * 2];
        #pragma unroll
        for (int mt = 0; mt < 2; mt++) {
            int rl0 = warp * 32 + mt * 16 + g;     // local row
            int c0  = nt * 8 + t4 * 2;
            hs[rl0 * 33 + c0]       = acc[mt][nt][0] + bv.x;
            hs[rl0 * 33 + c0 + 1]   = acc[mt][nt][1] + bv.y;
            hs[(rl0 + 8) * 33 + c0]     = acc[mt][nt][2] + bv.x;
            hs[(rl0 + 8) * 33 + c0 + 1] = acc[mt][nt][3] + bv.y;
        }
    }
    __syncthreads();

    // ---- KAN phase: one thread per row ----
    const int row = blockIdx.x * TMROWS + tid;
    if (row >= N) return;

    float xs[32];
    #pragma unroll
    for (int i = 0; i < 32; i++) xs[i] = hs[tid * 33 + i];   // (tid+i)%32 banks: conflict-free

    // layer 0: 32 -> 6 (padded to 8, f32x2 accumulation)
    uint64_t kacc[4];
    kacc[0] = kacc[1] = kacc[2] = kacc[3] = 0ull;

    #pragma unroll
    for (int i = 0; i < 32; i++) {
        float x  = xs[i];
        float sg = silu_f(x);
        uint64_t sgd = f2dup(sg);
        const uint64_t* wbp = (const uint64_t*)&wb0s[i * 8];
        ffma2(kacc[0], sgd, wbp[0]); ffma2(kacc[1], sgd, wbp[1]);
        ffma2(kacc[2], sgd, wbp[2]); ffma2(kacc[3], sgd, wbp[3]);

        float t = (x + 2.f) * 4.f;
        if (t >= 0.f && t < 16.f) {
            float cf = floorf(t);
            int   c  = (int)cf;
            float u  = t - cf;
            float bw[5];
            bspline4(u, bw);
            #pragma unroll
            for (int k = 0; k < 5; k++) {
                int j = c - 4 + k;
                if (j >= 0 && j < 12) {
                    uint64_t bd = f2dup(bw[k]);
                    const uint64_t* cp = (const uint64_t*)&cw0s[i * 96 + j * 8];
                    ffma2(kacc[0], bd, cp[0]); ffma2(kacc[1], bd, cp[1]);
                    ffma2(kacc[2], bd, cp[2]); ffma2(kacc[3], bd, cp[3]);
                }
            }
        }
    }
    float hh[6], u0, u1;
    f2unpack(kacc[0], hh[0], hh[1]);
    f2unpack(kacc[1], hh[2], hh[3]);
    f2unpack(kacc[2], u0, u1); hh[4] = u0; hh[5] = u1;

    // layer 1: 6 -> 1
    float res = b1s[0];
    #pragma unroll
    for (int i = 0; i < 6; i++) {
        float x = hh[i] + b0s[i];
        res += silu_f(x) * wb1s[i];
        float t = (x + 2.f) * 4.f;
        if (t >= 0.f && t < 16.f) {
            float cf = floorf(t);
            int   c  = (int)cf;
            float u  = t - cf;
            float bw[5];
            bspline4(u, bw);
            #pragma unroll
            for (int k = 0; k < 5; k++) {
                int j = c - 4 + k;
                if (j >= 0 && j < 12) res += bw[k] * cw1s[i * 12 + j];
            }
        }
    }
    out[row] = res;
}

// ---------------------------------------------------------------------------
// Launch
// ---------------------------------------------------------------------------
extern "C" void kernel_launch(void* const* d_in, const int* in_sizes, int n_in,
                              void* d_out, int out_size)
{
    const float* node_rep = (const float*)d_in[0];
    const float* mlp_w    = (const float*)d_in[1];
    const float* mlp_b    = (const float*)d_in[2];
    const float* coef0    = (const float*)d_in[3];
    const float* wb0      = (const float*)d_in[4];
    const float* ws0      = (const float*)d_in[5];
    const float* b0       = (const float*)d_in[6];
    const float* coef1    = (const float*)d_in[7];
    const float* wb1      = (const float*)d_in[8];
    const float* ws1      = (const float*)d_in[9];
    const float* b1       = (const float*)d_in[10];

    int N = in_sizes[0] / D_IN;

    wfrag_kernel<<<(NKS * 4 * 32 + 255) / 256, 256>>>(mlp_w);
    fused_kernel<<<(N + TMROWS - 1) / TMROWS, 256>>>(
        node_rep, mlp_b, coef0, wb0, ws0, b0, coef1, wb1, ws1, b1,
        (float*)d_out, N);
}